// round 7
// baseline (speedup 1.0000x reference)
#include <cuda_runtime.h>
#include <cstdint>

// Problem constants
#define B_DIM   16
#define L_DIM   160000
#define N_WT    10
#define WT_LEN  512
#define FIR_TAPS 31
#define WT_TOT  (N_WT * WT_LEN)

// Blocked-scan parameters (XLA ReduceWindowRewriter, base_length = 16)
#define NS1 10000
#define NS2 625
#define NS3 40
#define NS4 3

#define TPB 640            // k_main threads per block (160000 / 640 = 250)

// k_main dynamic smem layout
#define SP_BYTES   (WT_TOT * 8)            // 40960  float2 pair table
#define SATT_BYTES (TPB * 11 * 4)          // 28160  padded attention tile
#define SINC_BYTES (TPB * 4)               // 2560   staged increments
#define SMEM_MAIN  (SP_BYTES + SATT_BYTES + SINC_BYTES)   // 71680

__device__ __forceinline__ float KF() { return (float)(512.0 / 16000.0); }

// Scratch
__device__ float  g_S1[B_DIM][NS1];   // 16-block sums of increments
__device__ float  g_O1[B_DIM][NS1];   // composed inclusive scan at level 1
__device__ float2 g_wtp[WT_TOT];      // FIR-filtered wavetable (value, next)

// ---------------------------------------------------------------------------
// k_s1: blocks x<40: S1 via coalesced pad-17 smem staging, strict sequential
// rn 16-sums (verified chain).  Block x==40,y==0: FIR + pair table.
// 40 blocks * 250 S1 entries = 10000; 40 * 4000 pitch = 160000 exactly.
// ---------------------------------------------------------------------------
__global__ void k_s1(const float* __restrict__ pitch,
                     const float* __restrict__ wtab,
                     const float* __restrict__ firh)
{
    __shared__ float st[250 * 17];          // 17000 B padded staging
    __shared__ float swt[WT_TOT];           // 20480 B (FIR block only)
    __shared__ float sh[FIR_TAPS];

    if (blockIdx.x == 40) {                 // FIR + pair block
        if (blockIdx.y != 0) return;
        if (threadIdx.x < FIR_TAPS) sh[threadIdx.x] = firh[threadIdx.x];
        __syncthreads();
        for (int idx = threadIdx.x; idx < WT_TOT; idx += blockDim.x) {
            int w = idx >> 9;
            int i = idx & 511;
            const float* row = wtab + w * WT_LEN;
            float s = 0.0f;
            #pragma unroll
            for (int k = 0; k < FIR_TAPS; k++) {
                int j = (i + k - 15 + WT_LEN) & 511;
                s = __fadd_rn(s, __fmul_rn(row[j], sh[k]));
            }
            swt[idx] = s;
        }
        __syncthreads();
        for (int idx = threadIdx.x; idx < WT_TOT; idx += blockDim.x) {
            int base_w = idx & ~511;
            int j = idx & 511;
            g_wtp[idx] = make_float2(swt[idx], swt[base_w | ((j + 1) & 511)]);
        }
        return;
    }

    const int b   = blockIdx.y;
    const int tid = threadIdx.x;
    const float k = KF();

    // coalesced load of 4000 pitch values, pre-multiplied, pad-17 scatter
    const float* P = pitch + b * L_DIM + blockIdx.x * 4000;
    for (int i = tid; i < 4000; i += 256) {
        float v = __fmul_rn(k, P[i]);
        st[(i >> 4) * 17 + (i & 15)] = v;
    }
    __syncthreads();

    // S1: strict sequential sum of 16 staged increments (conflict-free LDS)
    if (tid < 250) {
        const float* row = st + tid * 17;
        float acc = 0.0f;
        #pragma unroll
        for (int e = 0; e < 16; e++)
            acc = __fadd_rn(acc, row[e]);
        g_S1[b][blockIdx.x * 250 + tid] = acc;
    }
}

// ---------------------------------------------------------------------------
// k_scan: one block per batch row.  Everything after S1:
//   stage S1 (pad-17 smem) -> S2 -> S3 -> S4 -> O4 -> O3 -> O2 (smem)
//   -> O1 computed in-place over the padded buffer -> coalesced writeout.
// All add chains: strict left-to-right __fadd_rn (verified bracketing).
// ---------------------------------------------------------------------------
__global__ void k_scan()
{
    __shared__ float s1p[NS2 * 17];         // 42500 B padded S1 (then O1)
    __shared__ float sS2[NS2];
    __shared__ float sS3[NS3];
    __shared__ float sS4[NS4];
    __shared__ float sO4[NS4];
    __shared__ float sO3[NS3];
    __shared__ float sO2[NS2];

    const int b   = blockIdx.x;
    const int tid = threadIdx.x;

    // stage S1 into pad-17 layout (coalesced LDG)
    for (int i = tid; i < NS1; i += 1024)
        s1p[(i >> 4) * 17 + (i & 15)] = g_S1[b][i];
    __syncthreads();

    // S2: strict sequential 16-sums (stride-17 rows: conflict-free)
    if (tid < NS2) {
        const float* row = s1p + tid * 17;
        float acc = 0.0f;
        #pragma unroll
        for (int e = 0; e < 16; e++)
            acc = __fadd_rn(acc, row[e]);
        sS2[tid] = acc;
    }
    __syncthreads();

    if (tid < NS3) {                         // S3 (625 padded to 640)
        float acc = 0.0f;
        for (int e = 0; e < 16; e++) {
            int idx = (tid << 4) + e;
            if (idx < NS2) acc = __fadd_rn(acc, sS2[idx]);
        }
        sS3[tid] = acc;
    }
    __syncthreads();

    if (tid < NS4) {                         // S4 (40 padded to 48)
        float acc = 0.0f;
        for (int e = 0; e < 16; e++) {
            int idx = (tid << 4) + e;
            if (idx < NS3) acc = __fadd_rn(acc, sS3[idx]);
        }
        sS4[tid] = acc;
    }
    __syncthreads();

    if (tid == 0) {                          // O4 sequential
        float acc = 0.0f;
        for (int m = 0; m < NS4; m++) {
            acc = __fadd_rn(acc, sS4[m]);
            sO4[m] = acc;
        }
    }
    __syncthreads();

    if (tid < NS3) {                         // O3
        int blk = tid >> 4;
        float acc = 0.0f;
        for (int m = (blk << 4); m <= tid; m++)
            acc = __fadd_rn(acc, sS3[m]);
        sO3[tid] = blk ? __fadd_rn(acc, sO4[blk - 1]) : acc;
    }
    __syncthreads();

    if (tid < NS2) {                         // O2
        int blk = tid >> 4;
        float acc = 0.0f;
        for (int m = (blk << 4); m <= tid; m++)
            acc = __fadd_rn(acc, sS2[m]);
        sO2[tid] = blk ? __fadd_rn(acc, sO3[blk - 1]) : acc;
    }
    __syncthreads();

    // O1 in place: thread j owns group j, running strict prefix
    if (tid < NS2) {
        float* row = s1p + tid * 17;
        float prev = (tid > 0) ? sO2[tid - 1] : 0.0f;
        float acc = 0.0f;
        #pragma unroll
        for (int e = 0; e < 16; e++) {
            acc = __fadd_rn(acc, row[e]);
            row[e] = (tid > 0) ? __fadd_rn(acc, prev) : acc;
        }
    }
    __syncthreads();

    // coalesced writeout
    for (int i = tid; i < NS1; i += 1024)
        g_O1[b][i] = s1p[(i >> 4) * 17 + (i & 15)];
}

// ---------------------------------------------------------------------------
// k_main: R4-verified arithmetic + (a) pre-paired wavetable loads,
// (b) attention staged via coalesced float4 -> stride-11 padded smem.
// ---------------------------------------------------------------------------
__global__ void __launch_bounds__(TPB) k_main(
        const float* __restrict__ pitch,
        const float* __restrict__ env,
        const float* __restrict__ att,
        float* __restrict__ out)
{
    extern __shared__ char smem_raw[];
    float2* sp   = (float2*)smem_raw;
    float*  satt = (float*)(smem_raw + SP_BYTES);
    float*  sinc = (float*)(smem_raw + SP_BYTES + SATT_BYTES);

    const int tid = threadIdx.x;
    const int b   = blockIdx.y;
    const int t   = blockIdx.x * TPB + tid;   // 250 * 640 == 160000
    const float k = KF();

    // pair table: coalesced float2 loads
    #pragma unroll
    for (int it = 0; it < WT_TOT / TPB; it++)
        sp[tid + it * TPB] = g_wtp[tid + it * TPB];

    // attention tile: coalesced float4 loads, scatter to stride-11 smem
    {
        const float4* ag = (const float4*)(att +
            (size_t)(b * (size_t)L_DIM + (size_t)blockIdx.x * TPB) * N_WT);
        #pragma unroll
        for (int it = 0; it < 3; it++) {
            int i = tid + it * TPB;
            if (i < (TPB * N_WT) / 4) {
                float4 v = ag[i];
                int e = i << 2;
                int q0 = (e    ) / 10; satt[q0*11 + (e     - q0*10)] = v.x;
                int q1 = (e + 1) / 10; satt[q1*11 + (e + 1 - q1*10)] = v.y;
                int q2 = (e + 2) / 10; satt[q2*11 + (e + 2 - q2*10)] = v.z;
                int q3 = (e + 3) / 10; satt[q3*11 + (e + 3 - q3*10)] = v.w;
            }
        }
    }

    // staged increments (16-blocks never straddle tiles: 640 % 16 == 0)
    sinc[tid] = __fmul_rn(k, pitch[b * L_DIM + t]);
    __syncthreads();

    // strict sequential prefix within the 16-block
    const int r0 = tid & 15;
    const int lb = tid & ~15;
    float acc = 0.0f;
    for (int e = 0; e <= r0; e++)
        acc = __fadd_rn(acc, sinc[lb + e]);
    const int j0 = t >> 4;
    float v = j0 ? __fadd_rn(acc, g_O1[b][j0 - 1]) : acc;

    // index = cumsum - rn(k * pitch_row0[t])
    float index = __fsub_rn(v, __fmul_rn(k, pitch[t]));

    // exact trunc-remainder by 512 (bitwise == fmodf) + jnp.remainder fixup
    float q = truncf(__fmul_rn(index, 0.001953125f));
    float r = __fmaf_rn(-512.0f, q, index);
    if (r < 0.0f) r = __fadd_rn(r, 512.0f);
    if (__fsub_rn(512.0f, r) < 1e-5f) r = 0.0f;

    float lof   = floorf(r);
    float alpha = __fsub_rn(r, lof);
    int   ilo   = (int)lof;

    const int base = b * L_DIM + t;
    float acc2 = 0.0f;
    #pragma unroll
    for (int w = 0; w < N_WT; w++) {
        float2 pr = sp[w * WT_LEN + ilo];
        float wave = __fadd_rn(pr.x, __fmul_rn(alpha, __fsub_rn(pr.y, pr.x)));
        acc2 = __fadd_rn(acc2, __fmul_rn(wave, satt[tid * 11 + w]));
    }
    out[base] = __fmul_rn(acc2, env[base]);
}

// ---------------------------------------------------------------------------
// d_in order: 0 pitch, 1 envelope, 2 attention, 3 wavetables, 4 fir_h
// ---------------------------------------------------------------------------
extern "C" void kernel_launch(void* const* d_in, const int* in_sizes, int n_in,
                              void* d_out, int out_size)
{
    const float* pitch = (const float*)d_in[0];
    const float* env   = (const float*)d_in[1];
    const float* att   = (const float*)d_in[2];
    const float* wtab  = (const float*)d_in[3];
    const float* firh  = (const float*)d_in[4];
    float* out = (float*)d_out;

    static bool attr_set = false;
    if (!attr_set) {
        cudaFuncSetAttribute(k_main, cudaFuncAttributeMaxDynamicSharedMemorySize,
                             SMEM_MAIN);
        attr_set = true;
    }

    k_s1<<<dim3(41, B_DIM), 256>>>(pitch, wtab, firh);
    k_scan<<<B_DIM, 1024>>>();
    k_main<<<dim3(250, B_DIM), TPB, SMEM_MAIN>>>(pitch, env, att, out);
}

// round 8
// speedup vs baseline: 1.2004x; 1.2004x over previous
#include <cuda_runtime.h>
#include <cstdint>

// Problem constants
#define B_DIM   16
#define L_DIM   160000
#define N_WT    10
#define WT_LEN  512
#define FIR_TAPS 31
#define WT_TOT  (N_WT * WT_LEN)

// Blocked-scan parameters (XLA ReduceWindowRewriter, base_length = 16)
#define NS1 10000
#define NS2 625
#define NS3 40
#define NS4 3

#define TPB 640            // k_main threads per block (160000 / 640 = 250)

__device__ __forceinline__ float KF() { return (float)(512.0 / 16000.0); }

// Scratch
__device__ float  g_S1[B_DIM][NS1];   // 16-block sums of increments
__device__ float  g_O1[B_DIM][NS1];   // composed inclusive scan at level 1
__device__ float  g_wt[WT_TOT];       // FIR-filtered wavetables

// ---------------------------------------------------------------------------
// k_s1: blocks x<40: S1 via coalesced pad-17 smem staging, strict sequential
// rn 16-sums (verified chain).  Block x==40,y==0: FIR.
// smem is a UNION of the two paths' buffers -> ~20.6 KB/block, 8 blocks/SM.
// ---------------------------------------------------------------------------
__global__ void k_s1(const float* __restrict__ pitch,
                     const float* __restrict__ wtab,
                     const float* __restrict__ firh)
{
    __shared__ union {
        float st[250 * 17];                             // 17000 B (S1 path)
        struct {
            float swt[WT_TOT];                          // 20480 B (FIR path)
            float sh[FIR_TAPS];
        } fir;
    } u;

    if (blockIdx.x == 40) {                 // FIR block
        if (blockIdx.y != 0) return;
        if (threadIdx.x < FIR_TAPS) u.fir.sh[threadIdx.x] = firh[threadIdx.x];
        // stage raw wavetables coalesced
        for (int idx = threadIdx.x; idx < WT_TOT; idx += blockDim.x)
            u.fir.swt[idx] = wtab[idx];
        __syncthreads();
        for (int idx = threadIdx.x; idx < WT_TOT; idx += blockDim.x) {
            int base_w = idx & ~511;
            int i = idx & 511;
            float s = 0.0f;
            #pragma unroll
            for (int k = 0; k < FIR_TAPS; k++) {
                int j = (i + k - 15 + WT_LEN) & 511;
                s = __fadd_rn(s, __fmul_rn(u.fir.swt[base_w | j], u.fir.sh[k]));
            }
            g_wt[idx] = s;
        }
        return;
    }

    const int b   = blockIdx.y;
    const int tid = threadIdx.x;
    const float k = KF();

    // coalesced load of 4000 pitch values, pre-multiplied, pad-17 scatter
    const float* P = pitch + b * L_DIM + blockIdx.x * 4000;
    #pragma unroll
    for (int it = 0; it < 16; it++) {
        int i = tid + it * 256;
        if (i < 4000) {
            float v = __fmul_rn(k, P[i]);
            u.st[(i >> 4) * 17 + (i & 15)] = v;
        }
    }
    __syncthreads();

    // S1: strict sequential sum of 16 staged increments (conflict-free LDS)
    if (tid < 250) {
        const float* row = u.st + tid * 17;
        float acc = 0.0f;
        #pragma unroll
        for (int e = 0; e < 16; e++)
            acc = __fadd_rn(acc, row[e]);
        g_S1[b][blockIdx.x * 250 + tid] = acc;
    }
}

// ---------------------------------------------------------------------------
// k_scan: one block per batch row.  Everything after S1:
//   stage S1 (pad-17 smem) -> S2 -> S3 -> S4 -> O4 -> O3 -> O2 (smem)
//   -> O1 computed in-place -> coalesced writeout.
// All add chains: strict left-to-right __fadd_rn (verified bracketing).
// ---------------------------------------------------------------------------
__global__ void k_scan()
{
    __shared__ float s1p[NS2 * 17];         // 42500 B padded S1 (then O1)
    __shared__ float sS2[NS2];
    __shared__ float sS3[NS3];
    __shared__ float sS4[NS4];
    __shared__ float sO4[NS4];
    __shared__ float sO3[NS3];
    __shared__ float sO2[NS2];

    const int b   = blockIdx.x;
    const int tid = threadIdx.x;

    for (int i = tid; i < NS1; i += 1024)
        s1p[(i >> 4) * 17 + (i & 15)] = g_S1[b][i];
    __syncthreads();

    if (tid < NS2) {                         // S2: strict 16-sums
        const float* row = s1p + tid * 17;
        float acc = 0.0f;
        #pragma unroll
        for (int e = 0; e < 16; e++)
            acc = __fadd_rn(acc, row[e]);
        sS2[tid] = acc;
    }
    __syncthreads();

    if (tid < NS3) {                         // S3 (625 padded to 640)
        float acc = 0.0f;
        for (int e = 0; e < 16; e++) {
            int idx = (tid << 4) + e;
            if (idx < NS2) acc = __fadd_rn(acc, sS2[idx]);
        }
        sS3[tid] = acc;
    }
    __syncthreads();

    if (tid < NS4) {                         // S4 (40 padded to 48)
        float acc = 0.0f;
        for (int e = 0; e < 16; e++) {
            int idx = (tid << 4) + e;
            if (idx < NS3) acc = __fadd_rn(acc, sS3[idx]);
        }
        sS4[tid] = acc;
    }
    __syncthreads();

    if (tid == 0) {                          // O4 sequential
        float acc = 0.0f;
        for (int m = 0; m < NS4; m++) {
            acc = __fadd_rn(acc, sS4[m]);
            sO4[m] = acc;
        }
    }
    __syncthreads();

    if (tid < NS3) {                         // O3
        int blk = tid >> 4;
        float acc = 0.0f;
        for (int m = (blk << 4); m <= tid; m++)
            acc = __fadd_rn(acc, sS3[m]);
        sO3[tid] = blk ? __fadd_rn(acc, sO4[blk - 1]) : acc;
    }
    __syncthreads();

    if (tid < NS2) {                         // O2
        int blk = tid >> 4;
        float acc = 0.0f;
        for (int m = (blk << 4); m <= tid; m++)
            acc = __fadd_rn(acc, sS2[m]);
        sO2[tid] = blk ? __fadd_rn(acc, sO3[blk - 1]) : acc;
    }
    __syncthreads();

    // O1 in place: thread j owns group j, running strict prefix
    if (tid < NS2) {
        float* row = s1p + tid * 17;
        float prev = (tid > 0) ? sO2[tid - 1] : 0.0f;
        float acc = 0.0f;
        #pragma unroll
        for (int e = 0; e < 16; e++) {
            acc = __fadd_rn(acc, row[e]);
            row[e] = (tid > 0) ? __fadd_rn(acc, prev) : acc;
        }
    }
    __syncthreads();

    for (int i = tid; i < NS1; i += 1024)
        g_O1[b][i] = s1p[(i >> 4) * 17 + (i & 15)];
}

// ---------------------------------------------------------------------------
// k_main: EXACT R4 version (measured 51.3us, rel_err 1.379262e-7).
// ---------------------------------------------------------------------------
__global__ void __launch_bounds__(TPB) k_main(
        const float* __restrict__ pitch,
        const float* __restrict__ env,
        const float* __restrict__ att,
        float* __restrict__ out)
{
    __shared__ float2 sp[WT_TOT];     // 40 KB pair table
    __shared__ float  sinc[TPB];      // staged increments

    const int tid = threadIdx.x;
    const int b   = blockIdx.y;
    const int t   = blockIdx.x * TPB + tid;   // 250 * 640 == 160000
    const float k = KF();

    // build (value, next-value) pair table; both reads coalesced
    for (int i = tid; i < WT_TOT; i += TPB) {
        int base_w = i & ~511;
        int j = i & 511;
        float lo = g_wt[i];
        float hi = g_wt[base_w | ((j + 1) & 511)];
        sp[i] = make_float2(lo, hi);
    }

    // stage this tile's increments (16-blocks never straddle tiles)
    sinc[tid] = __fmul_rn(k, pitch[b * L_DIM + t]);
    __syncthreads();

    // strict sequential prefix within the 16-block
    const int r0 = tid & 15;
    const int lb = tid & ~15;
    float acc = 0.0f;
    for (int e = 0; e <= r0; e++)
        acc = __fadd_rn(acc, sinc[lb + e]);
    const int j0 = t >> 4;
    float v = j0 ? __fadd_rn(acc, g_O1[b][j0 - 1]) : acc;

    // index = cumsum - rn(k * pitch_row0[t])
    float index = __fsub_rn(v, __fmul_rn(k, pitch[t]));

    // exact trunc-remainder by 512 (bitwise == fmodf) + jnp.remainder fixup
    float q = truncf(__fmul_rn(index, 0.001953125f));
    float r = __fmaf_rn(-512.0f, q, index);
    if (r < 0.0f) r = __fadd_rn(r, 512.0f);
    if (__fsub_rn(512.0f, r) < 1e-5f) r = 0.0f;

    float lof   = floorf(r);
    float alpha = __fsub_rn(r, lof);
    int   ilo   = (int)lof;

    const int base = b * L_DIM + t;
    const float2* ap = (const float2*)(att + (size_t)base * N_WT);
    float2 a0 = ap[0], a1 = ap[1], a2 = ap[2], a3 = ap[3], a4 = ap[4];
    float aw[N_WT] = {a0.x, a0.y, a1.x, a1.y, a2.x, a2.y, a3.x, a3.y, a4.x, a4.y};

    float acc2 = 0.0f;
    #pragma unroll
    for (int w = 0; w < N_WT; w++) {
        float2 pr = sp[w * WT_LEN + ilo];
        float wave = __fadd_rn(pr.x, __fmul_rn(alpha, __fsub_rn(pr.y, pr.x)));
        acc2 = __fadd_rn(acc2, __fmul_rn(wave, aw[w]));
    }
    out[base] = __fmul_rn(acc2, env[base]);
}

// ---------------------------------------------------------------------------
// d_in order: 0 pitch, 1 envelope, 2 attention, 3 wavetables, 4 fir_h
// ---------------------------------------------------------------------------
extern "C" void kernel_launch(void* const* d_in, const int* in_sizes, int n_in,
                              void* d_out, int out_size)
{
    const float* pitch = (const float*)d_in[0];
    const float* env   = (const float*)d_in[1];
    const float* att   = (const float*)d_in[2];
    const float* wtab  = (const float*)d_in[3];
    const float* firh  = (const float*)d_in[4];
    float* out = (float*)d_out;

    k_s1<<<dim3(41, B_DIM), 256>>>(pitch, wtab, firh);
    k_scan<<<B_DIM, 1024>>>();
    k_main<<<dim3(250, B_DIM), TPB>>>(pitch, env, att, out);
}

// round 9
// speedup vs baseline: 1.3646x; 1.1368x over previous
#include <cuda_runtime.h>
#include <cstdint>

// Problem constants
#define B_DIM   16
#define L_DIM   160000
#define N_WT    10
#define WT_LEN  512
#define FIR_TAPS 31
#define WT_TOT  (N_WT * WT_LEN)

// Blocked-scan parameters (XLA ReduceWindowRewriter, base_length = 16)
#define NS1 10000
#define NS2 625
#define NS3 40
#define NS4 3

// k_main tiling: 640 threads x 5 samples = 3200-sample tiles, 50 tiles/row
#define TPB   640
#define SAMP  5
#define TILE  (TPB * SAMP)          // 3200

// k_s1 tiling: 80 tiles/row, 2000 pitch values -> 125 S1 groups per tile
#define S1_TILES 80
#define S1_PITCH 2000
#define S1_GRP   125

// k_main dynamic smem: pair table + staged increments
#define SP_BYTES   (WT_TOT * 8)     // 40960
#define SINC_BYTES (TILE * 4)       // 12800
#define SMEM_MAIN  (SP_BYTES + SINC_BYTES)   // 53760

__device__ __forceinline__ float KF() { return (float)(512.0 / 16000.0); }

// Scratch
__device__ float  g_S1[B_DIM][NS1];   // 16-block sums of increments
__device__ float  g_O1[B_DIM][NS1];   // composed inclusive scan at level 1
__device__ float  g_wt[WT_TOT];       // FIR-filtered wavetables
__device__ float4 g_wtp4[WT_TOT / 2]; // packed (lo,hi) pairs, 2 per float4

// ---------------------------------------------------------------------------
// k_s1: blocks x<80: S1 via coalesced pad-17 smem staging, strict sequential
// rn 16-sums (verified chain).  Block x==80,y==0: FIR + pair table.
// ---------------------------------------------------------------------------
__global__ void k_s1(const float* __restrict__ pitch,
                     const float* __restrict__ wtab,
                     const float* __restrict__ firh)
{
    __shared__ union {
        float st[S1_GRP * 17];                          // 8500 B (S1 path)
        struct {
            float swt[WT_TOT];                          // 20480 B (FIR path)
            float sh[FIR_TAPS];
        } fir;
    } u;

    if (blockIdx.x == S1_TILES) {           // FIR + pair block
        if (blockIdx.y != 0) return;
        if (threadIdx.x < FIR_TAPS) u.fir.sh[threadIdx.x] = firh[threadIdx.x];
        for (int idx = threadIdx.x; idx < WT_TOT; idx += blockDim.x)
            u.fir.swt[idx] = wtab[idx];
        __syncthreads();
        for (int idx = threadIdx.x; idx < WT_TOT; idx += blockDim.x) {
            int base_w = idx & ~511;
            int i = idx & 511;
            float s = 0.0f;
            #pragma unroll
            for (int k = 0; k < FIR_TAPS; k++) {
                int j = (i + k - 15 + WT_LEN) & 511;
                s = __fadd_rn(s, __fmul_rn(u.fir.swt[base_w | j], u.fir.sh[k]));
            }
            g_wt[idx] = s;
        }
        __syncthreads();   // block-scope ordering of g_wt writes vs reads
        // pack (value, next) pairs, two per float4
        for (int p = threadIdx.x; p < WT_TOT / 2; p += blockDim.x) {
            int i0 = 2 * p, i1 = 2 * p + 1;
            int bw0 = i0 & ~511, bw1 = i1 & ~511;
            float4 v;
            v.x = g_wt[i0]; v.y = g_wt[bw0 | ((i0 + 1) & 511)];
            v.z = g_wt[i1]; v.w = g_wt[bw1 | ((i1 + 1) & 511)];
            g_wtp4[p] = v;
        }
        return;
    }

    const int b   = blockIdx.y;
    const int tid = threadIdx.x;
    const float k = KF();

    // coalesced load of 2000 pitch values, pre-multiplied, pad-17 scatter
    const float* P = pitch + b * L_DIM + blockIdx.x * S1_PITCH;
    for (int i = tid; i < S1_PITCH; i += 256) {
        float v = __fmul_rn(k, P[i]);
        u.st[(i >> 4) * 17 + (i & 15)] = v;
    }
    __syncthreads();

    // S1: strict sequential sum of 16 staged increments (conflict-free LDS)
    if (tid < S1_GRP) {
        const float* row = u.st + tid * 17;
        float acc = 0.0f;
        #pragma unroll
        for (int e = 0; e < 16; e++)
            acc = __fadd_rn(acc, row[e]);
        g_S1[b][blockIdx.x * S1_GRP + tid] = acc;
    }
}

// ---------------------------------------------------------------------------
// k_scan: one block per batch row.  Everything after S1 (verified chain):
//   stage S1 (pad-17) -> S2 -> S3 -> S4 -> O4 -> O3 -> O2 -> O1 -> writeout.
// ---------------------------------------------------------------------------
__global__ void k_scan()
{
    __shared__ float s1p[NS2 * 17];
    __shared__ float sS2[NS2];
    __shared__ float sS3[NS3];
    __shared__ float sS4[NS4];
    __shared__ float sO4[NS4];
    __shared__ float sO3[NS3];
    __shared__ float sO2[NS2];

    const int b   = blockIdx.x;
    const int tid = threadIdx.x;

    for (int i = tid; i < NS1; i += 1024)
        s1p[(i >> 4) * 17 + (i & 15)] = g_S1[b][i];
    __syncthreads();

    if (tid < NS2) {
        const float* row = s1p + tid * 17;
        float acc = 0.0f;
        #pragma unroll
        for (int e = 0; e < 16; e++)
            acc = __fadd_rn(acc, row[e]);
        sS2[tid] = acc;
    }
    __syncthreads();

    if (tid < NS3) {
        float acc = 0.0f;
        for (int e = 0; e < 16; e++) {
            int idx = (tid << 4) + e;
            if (idx < NS2) acc = __fadd_rn(acc, sS2[idx]);
        }
        sS3[tid] = acc;
    }
    __syncthreads();

    if (tid < NS4) {
        float acc = 0.0f;
        for (int e = 0; e < 16; e++) {
            int idx = (tid << 4) + e;
            if (idx < NS3) acc = __fadd_rn(acc, sS3[idx]);
        }
        sS4[tid] = acc;
    }
    __syncthreads();

    if (tid == 0) {
        float acc = 0.0f;
        for (int m = 0; m < NS4; m++) {
            acc = __fadd_rn(acc, sS4[m]);
            sO4[m] = acc;
        }
    }
    __syncthreads();

    if (tid < NS3) {
        int blk = tid >> 4;
        float acc = 0.0f;
        for (int m = (blk << 4); m <= tid; m++)
            acc = __fadd_rn(acc, sS3[m]);
        sO3[tid] = blk ? __fadd_rn(acc, sO4[blk - 1]) : acc;
    }
    __syncthreads();

    if (tid < NS2) {
        int blk = tid >> 4;
        float acc = 0.0f;
        for (int m = (blk << 4); m <= tid; m++)
            acc = __fadd_rn(acc, sS2[m]);
        sO2[tid] = blk ? __fadd_rn(acc, sO3[blk - 1]) : acc;
    }
    __syncthreads();

    if (tid < NS2) {
        float* row = s1p + tid * 17;
        float prev = (tid > 0) ? sO2[tid - 1] : 0.0f;
        float acc = 0.0f;
        #pragma unroll
        for (int e = 0; e < 16; e++) {
            acc = __fadd_rn(acc, row[e]);
            row[e] = (tid > 0) ? __fadd_rn(acc, prev) : acc;
        }
    }
    __syncthreads();

    for (int i = tid; i < NS1; i += 1024)
        g_O1[b][i] = s1p[(i >> 4) * 17 + (i & 15)];
}

// ---------------------------------------------------------------------------
// k_main: 3200-sample tiles (5 samples/thread) to amortize the pair-table
// fill; fill via float4 from g_wtp4.  Per-sample arithmetic is the EXACT
// R4-verified chain (prefix, O1 compose, remainder, interp, dot, envelope).
// ---------------------------------------------------------------------------
__global__ void __launch_bounds__(TPB, 3) k_main(
        const float* __restrict__ pitch,
        const float* __restrict__ env,
        const float* __restrict__ att,
        float* __restrict__ out)
{
    extern __shared__ char smem_raw[];
    float2* sp   = (float2*)smem_raw;
    float*  sinc = (float*)(smem_raw + SP_BYTES);

    const int tid = threadIdx.x;
    const int b   = blockIdx.y;
    const int base_t = blockIdx.x * TILE;
    const float k = KF();

    // pair-table fill: 4 x LDG.128 per thread
    {
        float4* sp4 = (float4*)sp;
        #pragma unroll
        for (int it = 0; it < (WT_TOT / 2) / TPB; it++)
            sp4[tid + it * TPB] = g_wtp4[tid + it * TPB];
    }

    // staged increments for the whole tile (16-groups never straddle: 3200%16==0)
    #pragma unroll
    for (int s = 0; s < SAMP; s++) {
        int m = tid + s * TPB;
        sinc[m] = __fmul_rn(k, pitch[b * L_DIM + base_t + m]);
    }
    __syncthreads();

    #pragma unroll 1
    for (int s = 0; s < SAMP; s++) {
        const int m = tid + s * TPB;
        const int t = base_t + m;

        // strict sequential prefix within the 16-group
        const int r0 = m & 15;
        const int lb = m & ~15;
        float acc = 0.0f;
        for (int e = 0; e <= r0; e++)
            acc = __fadd_rn(acc, sinc[lb + e]);
        const int j0 = t >> 4;
        float v = j0 ? __fadd_rn(acc, g_O1[b][j0 - 1]) : acc;

        // index = cumsum - rn(k * pitch_row0[t])
        float index = __fsub_rn(v, __fmul_rn(k, pitch[t]));

        // exact trunc-remainder by 512 (bitwise == fmodf) + jnp.remainder fixup
        float q = truncf(__fmul_rn(index, 0.001953125f));
        float r = __fmaf_rn(-512.0f, q, index);
        if (r < 0.0f) r = __fadd_rn(r, 512.0f);
        if (__fsub_rn(512.0f, r) < 1e-5f) r = 0.0f;

        float lof   = floorf(r);
        float alpha = __fsub_rn(r, lof);
        int   ilo   = (int)lof;

        const int basei = b * L_DIM + t;
        const float2* ap = (const float2*)(att + (size_t)basei * N_WT);
        float2 a0 = ap[0], a1 = ap[1], a2 = ap[2], a3 = ap[3], a4 = ap[4];
        float aw[N_WT] = {a0.x, a0.y, a1.x, a1.y, a2.x,
                          a2.y, a3.x, a3.y, a4.x, a4.y};

        float acc2 = 0.0f;
        #pragma unroll
        for (int w = 0; w < N_WT; w++) {
            float2 pr = sp[w * WT_LEN + ilo];
            float wave = __fadd_rn(pr.x, __fmul_rn(alpha, __fsub_rn(pr.y, pr.x)));
            acc2 = __fadd_rn(acc2, __fmul_rn(wave, aw[w]));
        }
        out[basei] = __fmul_rn(acc2, env[basei]);
    }
}

// ---------------------------------------------------------------------------
// d_in order: 0 pitch, 1 envelope, 2 attention, 3 wavetables, 4 fir_h
// ---------------------------------------------------------------------------
extern "C" void kernel_launch(void* const* d_in, const int* in_sizes, int n_in,
                              void* d_out, int out_size)
{
    const float* pitch = (const float*)d_in[0];
    const float* env   = (const float*)d_in[1];
    const float* att   = (const float*)d_in[2];
    const float* wtab  = (const float*)d_in[3];
    const float* firh  = (const float*)d_in[4];
    float* out = (float*)d_out;

    cudaFuncSetAttribute(k_main, cudaFuncAttributeMaxDynamicSharedMemorySize,
                         SMEM_MAIN);

    k_s1<<<dim3(S1_TILES + 1, B_DIM), 256>>>(pitch, wtab, firh);
    k_scan<<<B_DIM, 1024>>>();
    k_main<<<dim3(L_DIM / TILE, B_DIM), TPB, SMEM_MAIN>>>(pitch, env, att, out);
}